// round 6
// baseline (speedup 1.0000x reference)
#include <cuda_runtime.h>

// Problem constants: B=2, L=2048 (Lq=Lk), E=1024, H=16, HD=64, M_LM=64
#define BATCH 2
#define LSEQ  2048
#define EMB   1024
#define MLM   64
#define NTOK  (BATCH * LSEQ)   // 4096

#define TILE 128
#define KT   16

// Scratch (static __device__ arrays — no allocations anywhere).
__device__ float g_vprojT[(long)BATCH * EMB * LSEQ];   // [b][e][k]   16.8 MB
__device__ float g_ql[(long)NTOK * MLM];               //             1 MB
__device__ float g_kl[(long)NTOK * MLM];               //             1 MB
__device__ float g_attn[(long)BATCH * LSEQ * LSEQ];    // [b][q][k]  33.5 MB
__device__ float g_out2[(long)BATCH * LSEQ * EMB];     //            16.8 MB

// ---------------------------------------------------------------------------
// Generic NT GEMM:  C[m,n] = sum_k A[m,k] * B[n,k]  (+ bias_m[m] + bias_n[n])
// A: [M x K] row-major, B: [N x K] row-major, C: [M x N] row-major (ldc = N).
// Batched via gridDim.z with element strides (0 = shared operand).
// Requires K % 16 == 0 and 16B-aligned rows (true for all uses: K in {64,1024,2048}).
// 128x128 tile, 256 threads, 8x8 register microtile.
// ---------------------------------------------------------------------------
__global__ __launch_bounds__(256, 2)
void gemm_nt_kernel(const float* __restrict__ A, const float* __restrict__ B,
                    float* __restrict__ C, int M, int N, int K,
                    long sA, long sB, long sC,
                    const float* __restrict__ bias_m,
                    const float* __restrict__ bias_n)
{
    __shared__ float As[KT][TILE + 4];
    __shared__ float Bs[KT][TILE + 4];

    A += (long)blockIdx.z * sA;
    B += (long)blockIdx.z * sB;
    C += (long)blockIdx.z * sC;

    const int m0  = blockIdx.y * TILE;
    const int n0  = blockIdx.x * TILE;
    const int tid = threadIdx.x;
    const int tx  = tid & 15;   // 16 cols of 8
    const int ty  = tid >> 4;   // 16 rows of 8

    float acc[8][8];
#pragma unroll
    for (int i = 0; i < 8; i++)
#pragma unroll
        for (int j = 0; j < 8; j++) acc[i][j] = 0.f;

    for (int kt = 0; kt < K; kt += KT) {
        // Load A and B tiles: 128x16 floats each = 512 float4 = 2 float4/thread.
#pragma unroll
        for (int r = 0; r < 2; r++) {
            int f   = tid + 256 * r;
            int row = f >> 2;
            int kq  = (f & 3) * 4;
            float4 va = make_float4(0.f, 0.f, 0.f, 0.f);
            if (m0 + row < M)
                va = *reinterpret_cast<const float4*>(A + (long)(m0 + row) * K + kt + kq);
            As[kq + 0][row] = va.x; As[kq + 1][row] = va.y;
            As[kq + 2][row] = va.z; As[kq + 3][row] = va.w;

            float4 vb = make_float4(0.f, 0.f, 0.f, 0.f);
            if (n0 + row < N)
                vb = *reinterpret_cast<const float4*>(B + (long)(n0 + row) * K + kt + kq);
            Bs[kq + 0][row] = vb.x; Bs[kq + 1][row] = vb.y;
            Bs[kq + 2][row] = vb.z; Bs[kq + 3][row] = vb.w;
        }
        __syncthreads();

#pragma unroll
        for (int k = 0; k < KT; k++) {
            // row length 132 floats -> 528B per k-row: 16B aligned, float4 OK.
            float4 a0 = *reinterpret_cast<const float4*>(&As[k][ty * 8]);
            float4 a1 = *reinterpret_cast<const float4*>(&As[k][ty * 8 + 4]);
            float4 b0 = *reinterpret_cast<const float4*>(&Bs[k][tx * 8]);
            float4 b1 = *reinterpret_cast<const float4*>(&Bs[k][tx * 8 + 4]);
            float a[8] = {a0.x, a0.y, a0.z, a0.w, a1.x, a1.y, a1.z, a1.w};
            float b[8] = {b0.x, b0.y, b0.z, b0.w, b1.x, b1.y, b1.z, b1.w};
#pragma unroll
            for (int i = 0; i < 8; i++)
#pragma unroll
                for (int j = 0; j < 8; j++)
                    acc[i][j] = fmaf(a[i], b[j], acc[i][j]);
        }
        __syncthreads();
    }

#pragma unroll
    for (int i = 0; i < 8; i++) {
        int m = m0 + ty * 8 + i;
        if (m >= M) continue;
        float bm = bias_m ? bias_m[m] : 0.f;
#pragma unroll
        for (int j = 0; j < 8; j++) {
            int n = n0 + tx * 8 + j;
            if (n < N)
                C[(long)m * N + n] = acc[i][j] + bm + (bias_n ? bias_n[n] : 0.f);
        }
    }
}

// ---------------------------------------------------------------------------
// Row softmax over 64 elements (landmark dim), scale 1/sqrt(64)=0.125 applied.
// One warp per row, in place.
// ---------------------------------------------------------------------------
__global__ __launch_bounds__(256)
void softmax64_kernel(float* __restrict__ X, int rows)
{
    int wrow = (blockIdx.x * blockDim.x + threadIdx.x) >> 5;
    int lane = threadIdx.x & 31;
    if (wrow >= rows) return;
    float* p = X + (long)wrow * 64;

    float v0 = p[lane] * 0.125f;
    float v1 = p[lane + 32] * 0.125f;
    float m = fmaxf(v0, v1);
#pragma unroll
    for (int o = 16; o; o >>= 1) m = fmaxf(m, __shfl_xor_sync(0xffffffffu, m, o));
    float e0 = __expf(v0 - m);
    float e1 = __expf(v1 - m);
    float s = e0 + e1;
#pragma unroll
    for (int o = 16; o; o >>= 1) s += __shfl_xor_sync(0xffffffffu, s, o);
    float inv = 1.0f / s;
    p[lane]      = e0 * inv;
    p[lane + 32] = e1 * inv;
}

// ---------------------------------------------------------------------------
// Row softmax over 2048 elements (key dim), scale 1/sqrt(HD)=0.125 applied.
// One 256-thread block per row, in place.
// ---------------------------------------------------------------------------
__global__ __launch_bounds__(256)
void softmax2048_kernel(float* __restrict__ X)
{
    float* p  = X + (long)blockIdx.x * 2048;
    int tid   = threadIdx.x;
    int lane  = tid & 31;
    int wid   = tid >> 5;
    __shared__ float red[8];

    float v[8];
    float m = -3.4e38f;
#pragma unroll
    for (int i = 0; i < 8; i++) {
        v[i] = p[tid + 256 * i] * 0.125f;
        m = fmaxf(m, v[i]);
    }
#pragma unroll
    for (int o = 16; o; o >>= 1) m = fmaxf(m, __shfl_xor_sync(0xffffffffu, m, o));
    if (lane == 0) red[wid] = m;
    __syncthreads();
    float mm = red[0];
#pragma unroll
    for (int w = 1; w < 8; w++) mm = fmaxf(mm, red[w]);

    float s = 0.f;
#pragma unroll
    for (int i = 0; i < 8; i++) {
        v[i] = __expf(v[i] - mm);
        s += v[i];
    }
#pragma unroll
    for (int o = 16; o; o >>= 1) s += __shfl_xor_sync(0xffffffffu, s, o);
    __syncthreads();              // red reuse
    if (lane == 0) red[wid] = s;
    __syncthreads();
    float ss = 0.f;
#pragma unroll
    for (int w = 0; w < 8; w++) ss += red[w];
    float inv = 1.0f / ss;
#pragma unroll
    for (int i = 0; i < 8; i++) p[tid + 256 * i] = v[i] * inv;
}

// ---------------------------------------------------------------------------
// Launch pipeline (graph-capturable: kernel launches only, no allocs/syncs).
// Input order (metadata): query, key, value, Wv, bv, Wl, bl, Wo, bo
// ---------------------------------------------------------------------------
extern "C" void kernel_launch(void* const* d_in, const int* in_sizes, int n_in,
                              void* d_out, int out_size)
{
    const float* query = (const float*)d_in[0];  // [2,2048,1024]
    const float* key   = (const float*)d_in[1];  // [2,2048,1024]
    const float* value = (const float*)d_in[2];  // [2,2048,1024]
    const float* Wv    = (const float*)d_in[3];  // [1024,1024]
    const float* bv    = (const float*)d_in[4];  // [1024]
    const float* Wl    = (const float*)d_in[5];  // [64,1024]
    const float* bl    = (const float*)d_in[6];  // [64]
    const float* Wo    = (const float*)d_in[7];  // [1024,1024]
    const float* bo    = (const float*)d_in[8];  // [1024]
    float* out = (float*)d_out;                  // [2,2048,1024]
    (void)in_sizes; (void)n_in; (void)out_size;

    float *vprojT, *ql, *kl, *attn, *out2;
    cudaGetSymbolAddress((void**)&vprojT, g_vprojT);
    cudaGetSymbolAddress((void**)&ql,     g_ql);
    cudaGetSymbolAddress((void**)&kl,     g_kl);
    cudaGetSymbolAddress((void**)&attn,   g_attn);
    cudaGetSymbolAddress((void**)&out2,   g_out2);

    dim3 blk(256);

    // 1) VprojT[b,e,k] = sum_c value[b,k,c]*Wv[e,c] + bv[e]
    //    NT: A=Wv [E x E], B=value[b] [L x E], C=vprojT[b] [E x L]
    gemm_nt_kernel<<<dim3(LSEQ / TILE, EMB / TILE, BATCH), blk>>>(
        Wv, value, vprojT, EMB, LSEQ, EMB,
        0L, (long)LSEQ * EMB, (long)EMB * LSEQ, bv, nullptr);

    // 2) Landmark projections: [NTOK x 64] = X[NTOK x E] @ Wl[64 x E]^T + bl
    gemm_nt_kernel<<<dim3(1, NTOK / TILE, 1), blk>>>(
        query, Wl, ql, NTOK, MLM, EMB, 0L, 0L, 0L, nullptr, bl);
    gemm_nt_kernel<<<dim3(1, NTOK / TILE, 1), blk>>>(
        key, Wl, kl, NTOK, MLM, EMB, 0L, 0L, 0L, nullptr, bl);

    // 3) Softmax over landmark dim (scale 1/8 fused)
    softmax64_kernel<<<(NTOK * 32 + 255) / 256, blk>>>(ql, NTOK);
    softmax64_kernel<<<(NTOK * 32 + 255) / 256, blk>>>(kl, NTOK);

    // 4) Scores: S[b,q,k] = sum_m ql[b,q,m]*kl[b,k,m]   (K=64)
    gemm_nt_kernel<<<dim3(LSEQ / TILE, LSEQ / TILE, BATCH), blk>>>(
        ql, kl, attn, LSEQ, LSEQ, MLM,
        (long)LSEQ * MLM, (long)LSEQ * MLM, (long)LSEQ * LSEQ, nullptr, nullptr);

    // 5) Softmax over key dim (scale 1/8 fused), in place
    softmax2048_kernel<<<BATCH * LSEQ, blk>>>(attn);

    // 6) out2[b,q,e] = sum_k attn[b,q,k] * vprojT[b,e,k]   (K=2048)
    gemm_nt_kernel<<<dim3(EMB / TILE, LSEQ / TILE, BATCH), blk>>>(
        attn, vprojT, out2, LSEQ, EMB, LSEQ,
        (long)LSEQ * LSEQ, (long)EMB * LSEQ, (long)LSEQ * EMB, nullptr, nullptr);

    // 7) out = out2 @ Wo^T + bo   (batches flattened: [NTOK x E])
    gemm_nt_kernel<<<dim3(EMB / TILE, NTOK / TILE, 1), blk>>>(
        out2, Wo, out, NTOK, EMB, EMB, 0L, 0L, 0L, nullptr, bo);
}

// round 10
// speedup vs baseline: 1.8841x; 1.8841x over previous
#include <cuda_runtime.h>
#include <cuda_bf16.h>
#include <stdint.h>

// Problem constants: B=2, L=2048, E=1024, M_LM=64
#define BATCH 2
#define LSEQ  2048
#define EMB   1024
#define MLM   64
#define NTOK  (BATCH * LSEQ)   // 4096

// GEMM tile config
#define TM 128
#define TN 128
#define KC 32          // bf16 K elements per smem chunk
#define GT 256         // threads per GEMM CTA
#define ROWB 80        // smem bytes per row (32 bf16 = 64B + 16B pad, 16B aligned)
#define TILEB (128 * ROWB)   // 10240 B per tile

// ---------------- device scratch (no allocations anywhere) ----------------
__device__ __nv_bfloat16 g_Wv_hi[EMB * EMB],   g_Wv_lo[EMB * EMB];
__device__ __nv_bfloat16 g_Wo_hi[EMB * EMB],   g_Wo_lo[EMB * EMB];
__device__ __nv_bfloat16 g_Wl_hi[MLM * EMB],   g_Wl_lo[MLM * EMB];
__device__ __nv_bfloat16 g_val_hi[NTOK * EMB], g_val_lo[NTOK * EMB];
__device__ __nv_bfloat16 g_q_hi[NTOK * EMB],   g_q_lo[NTOK * EMB];
__device__ __nv_bfloat16 g_k_hi[NTOK * EMB],   g_k_lo[NTOK * EMB];
__device__ __nv_bfloat16 g_vpT_hi[(long)BATCH * EMB * LSEQ], g_vpT_lo[(long)BATCH * EMB * LSEQ];
__device__ float         g_qlf[NTOK * MLM],    g_klf[NTOK * MLM];
__device__ __nv_bfloat16 g_ql_hi[NTOK * MLM],  g_ql_lo[NTOK * MLM];
__device__ __nv_bfloat16 g_kl_hi[NTOK * MLM],  g_kl_lo[NTOK * MLM];
__device__ float         g_attn[(long)BATCH * LSEQ * LSEQ];
__device__ __nv_bfloat16 g_attn_hi[(long)BATCH * LSEQ * LSEQ], g_attn_lo[(long)BATCH * LSEQ * LSEQ];
__device__ __nv_bfloat16 g_out2_hi[NTOK * EMB], g_out2_lo[NTOK * EMB];

// ---------------- helpers ----------------
__device__ __forceinline__ uint32_t smem_u32(const void* p) {
    uint32_t a;
    asm("{ .reg .u64 t; cvta.to.shared.u64 t, %1; cvt.u32.u64 %0, t; }" : "=r"(a) : "l"(p));
    return a;
}
__device__ __forceinline__ void ldsm4(uint32_t* r, uint32_t addr) {
    asm volatile("ldmatrix.sync.aligned.m8n8.x4.shared.b16 {%0,%1,%2,%3}, [%4];"
                 : "=r"(r[0]), "=r"(r[1]), "=r"(r[2]), "=r"(r[3]) : "r"(addr));
}
__device__ __forceinline__ void mma_bf16(float* c, const uint32_t* a,
                                         uint32_t b0, uint32_t b1) {
    asm volatile(
        "mma.sync.aligned.m16n8k16.row.col.f32.bf16.bf16.f32 "
        "{%0,%1,%2,%3}, {%4,%5,%6,%7}, {%8,%9}, {%0,%1,%2,%3};"
        : "+f"(c[0]), "+f"(c[1]), "+f"(c[2]), "+f"(c[3])
        : "r"(a[0]), "r"(a[1]), "r"(a[2]), "r"(a[3]), "r"(b0), "r"(b1));
}
__device__ __forceinline__ uint32_t pack_bf(float a, float b) {
    __nv_bfloat16 ha = __float2bfloat16(a), hb = __float2bfloat16(b);
    return (uint32_t)__bfloat16_as_ushort(ha) | ((uint32_t)__bfloat16_as_ushort(hb) << 16);
}

// ---------------------------------------------------------------------------
// bf16-split NT GEMM on HMMA (mma.sync m16n8k16):
//   C[m,n] = sum_k (Ahi+Alo)[m,k]*(Bhi+Blo)[n,k]   (3-term split, fp32 accum)
// A*: [M x K] bf16 row-major, B*: [N x K] bf16 row-major.
// Output: Cf != null -> fp32 (+biases); else bf16 hi/lo split pair.
// Requires K % 32 == 0, rows 16B-aligned. M,N tiles padded by zero-fill.
// 128x128 CTA tile, 256 threads = 8 warps (2 x 4), warp tile 64x32.
// ---------------------------------------------------------------------------
__global__ __launch_bounds__(GT, 2)
void gemm_tc_kernel(const __nv_bfloat16* __restrict__ Ahi, const __nv_bfloat16* __restrict__ Alo,
                    const __nv_bfloat16* __restrict__ Bhi, const __nv_bfloat16* __restrict__ Blo,
                    float* __restrict__ Cf,
                    __nv_bfloat16* __restrict__ Chi, __nv_bfloat16* __restrict__ Clo,
                    int M, int N, int K,
                    long sA, long sB, long sC,
                    const float* __restrict__ bias_m, const float* __restrict__ bias_n)
{
    __shared__ __align__(16) char smem[4 * TILEB];   // Ah, Al, Bh, Bl

    const int tid  = threadIdx.x;
    const int wid  = tid >> 5;
    const int lane = tid & 31;
    const int wm   = wid >> 2;       // 0..1  (64-row half)
    const int wn   = wid & 3;        // 0..3  (32-col quarter)
    const uint32_t sb = smem_u32(smem);
    const uint32_t sAh = sb, sAl = sb + TILEB, sBh = sb + 2 * TILEB, sBl = sb + 3 * TILEB;

    const long bz = blockIdx.z;
    Ahi += bz * sA;  Alo += bz * sA;
    Bhi += bz * sB;  Blo += bz * sB;
    if (Cf) Cf += bz * sC; else { Chi += bz * sC; Clo += bz * sC; }

    const int m0 = blockIdx.y * TM;
    const int n0 = blockIdx.x * TN;

    float acc[4][4][4];
#pragma unroll
    for (int i = 0; i < 4; i++)
#pragma unroll
        for (int j = 0; j < 4; j++)
#pragma unroll
            for (int r = 0; r < 4; r++) acc[i][j][r] = 0.f;

    // tile loader: 128 rows x 32 bf16 (64B/row) -> smem rows of 80B, zero-fill OOB
    auto load_tile = [&](const __nv_bfloat16* src, int r0, int R, int kt, int toff) {
#pragma unroll
        for (int it = 0; it < 2; it++) {
            int id  = tid + GT * it;       // 0..511
            int row = id >> 2;
            int seg = id & 3;              // 16B segment
            uint4 v = make_uint4(0u, 0u, 0u, 0u);
            int gr = r0 + row;
            if (gr < R)
                v = *reinterpret_cast<const uint4*>(src + (long)gr * K + kt + seg * 8);
            *reinterpret_cast<uint4*>(smem + toff + row * ROWB + seg * 16) = v;
        }
    };

    // ldmatrix lane addressing (shared across frags): row offset lane&15, col half lane>>4
    const int lrow = (lane & 15);
    const int lcol = ((lane >> 4) << 3) * 2;   // byte offset of k-half (0 or 16B)

    for (int kt = 0; kt < K; kt += KC) {
        load_tile(Ahi, m0, M, kt, 0);
        load_tile(Alo, m0, M, kt, TILEB);
        load_tile(Bhi, n0, N, kt, 2 * TILEB);
        load_tile(Blo, n0, N, kt, 3 * TILEB);
        __syncthreads();

#pragma unroll
        for (int ks = 0; ks < 2; ks++) {
            const uint32_t kb = ks * 32 + lcol;    // byte offset within row

            // A_hi fragments: 4 x (16x16)
            uint32_t ah[4][4];
#pragma unroll
            for (int mi = 0; mi < 4; mi++)
                ldsm4(ah[mi], sAh + (uint32_t)(wm * 64 + mi * 16 + lrow) * ROWB + kb);

            // B_hi fragments: 2 x ldmatrix.x4 -> 4 n-frags of (8x16)
            // regs {r0,r2} = frag nb*2, {r1,r3} = frag nb*2+1
            uint32_t bh[4][2];
#pragma unroll
            for (int nb = 0; nb < 2; nb++) {
                uint32_t t[4];
                ldsm4(t, sBh + (uint32_t)(wn * 32 + nb * 16 + lrow) * ROWB + kb);
                bh[nb * 2 + 0][0] = t[0]; bh[nb * 2 + 0][1] = t[2];
                bh[nb * 2 + 1][0] = t[1]; bh[nb * 2 + 1][1] = t[3];
            }

            // hi * hi
#pragma unroll
            for (int mi = 0; mi < 4; mi++)
#pragma unroll
                for (int f = 0; f < 4; f++)
                    mma_bf16(acc[mi][f], ah[mi], bh[f][0], bh[f][1]);

            // lo * hi (stream A_lo one fragment at a time)
#pragma unroll
            for (int mi = 0; mi < 4; mi++) {
                uint32_t al[4];
                ldsm4(al, sAl + (uint32_t)(wm * 64 + mi * 16 + lrow) * ROWB + kb);
#pragma unroll
                for (int f = 0; f < 4; f++)
                    mma_bf16(acc[mi][f], al, bh[f][0], bh[f][1]);
            }

            // hi * lo (stream B_lo)
#pragma unroll
            for (int nb = 0; nb < 2; nb++) {
                uint32_t t[4];
                ldsm4(t, sBl + (uint32_t)(wn * 32 + nb * 16 + lrow) * ROWB + kb);
#pragma unroll
                for (int mi = 0; mi < 4; mi++) {
                    mma_bf16(acc[mi][nb * 2 + 0], ah[mi], t[0], t[2]);
                    mma_bf16(acc[mi][nb * 2 + 1], ah[mi], t[1], t[3]);
                }
            }
        }
        __syncthreads();
    }

    // Epilogue. c0,c1 -> row lane>>2, cols (lane&3)*2 +{0,1}; c2,c3 -> row+8.
    const int rbase = m0 + wm * 64 + (lane >> 2);
    const int cbase = n0 + wn * 32 + (lane & 3) * 2;
#pragma unroll
    for (int mi = 0; mi < 4; mi++) {
#pragma unroll
        for (int half = 0; half < 2; half++) {
            int m = rbase + mi * 16 + half * 8;
            if (m >= M) continue;
            float bm = bias_m ? bias_m[m] : 0.f;
#pragma unroll
            for (int f = 0; f < 4; f++) {
                int n = cbase + f * 8;
                if (n >= N) continue;
                float f0 = acc[mi][f][half * 2 + 0] + bm + (bias_n ? bias_n[n] : 0.f);
                float f1 = acc[mi][f][half * 2 + 1] + bm + (bias_n ? bias_n[n + 1] : 0.f);
                long o = (long)m * N + n;
                if (Cf) {
                    *reinterpret_cast<float2*>(Cf + o) = make_float2(f0, f1);
                } else {
                    __nv_bfloat16 h0 = __float2bfloat16(f0), h1 = __float2bfloat16(f1);
                    uint32_t hv = (uint32_t)__bfloat16_as_ushort(h0) |
                                  ((uint32_t)__bfloat16_as_ushort(h1) << 16);
                    uint32_t lv = pack_bf(f0 - __bfloat162float(h0), f1 - __bfloat162float(h1));
                    *reinterpret_cast<uint32_t*>(Chi + o) = hv;
                    *reinterpret_cast<uint32_t*>(Clo + o) = lv;
                }
            }
        }
    }
}

// ---------------------------------------------------------------------------
// fp32 -> (hi, lo) bf16 split, vectorized float4
// ---------------------------------------------------------------------------
__global__ __launch_bounds__(256)
void split_kernel(const float4* __restrict__ x, uint2* __restrict__ hi,
                  uint2* __restrict__ lo, int n4)
{
    int i = blockIdx.x * 256 + threadIdx.x;
    if (i >= n4) return;
    float4 v = x[i];
    __nv_bfloat16 h0 = __float2bfloat16(v.x), h1 = __float2bfloat16(v.y);
    __nv_bfloat16 h2 = __float2bfloat16(v.z), h3 = __float2bfloat16(v.w);
    uint2 hv, lv;
    hv.x = (uint32_t)__bfloat16_as_ushort(h0) | ((uint32_t)__bfloat16_as_ushort(h1) << 16);
    hv.y = (uint32_t)__bfloat16_as_ushort(h2) | ((uint32_t)__bfloat16_as_ushort(h3) << 16);
    lv.x = pack_bf(v.x - __bfloat162float(h0), v.y - __bfloat162float(h1));
    lv.y = pack_bf(v.z - __bfloat162float(h2), v.w - __bfloat162float(h3));
    hi[i] = hv;
    lo[i] = lv;
}

// ---------------------------------------------------------------------------
// softmax over 64 (landmark dim), scale 1/8; fp32 in, bf16 hi/lo out.
// One warp per row.
// ---------------------------------------------------------------------------
__global__ __launch_bounds__(256)
void softmax64_kernel(const float* __restrict__ X, __nv_bfloat16* __restrict__ Hi,
                      __nv_bfloat16* __restrict__ Lo, int rows)
{
    int wrow = (blockIdx.x * blockDim.x + threadIdx.x) >> 5;
    int lane = threadIdx.x & 31;
    if (wrow >= rows) return;
    const float* p = X + (long)wrow * 64;
    float v0 = p[lane] * 0.125f;
    float v1 = p[lane + 32] * 0.125f;
    float m = fmaxf(v0, v1);
#pragma unroll
    for (int o = 16; o; o >>= 1) m = fmaxf(m, __shfl_xor_sync(0xffffffffu, m, o));
    float e0 = __expf(v0 - m), e1 = __expf(v1 - m);
    float s = e0 + e1;
#pragma unroll
    for (int o = 16; o; o >>= 1) s += __shfl_xor_sync(0xffffffffu, s, o);
    float inv = 1.0f / s;
    float o0 = e0 * inv, o1 = e1 * inv;
    __nv_bfloat16 h0 = __float2bfloat16(o0), h1 = __float2bfloat16(o1);
    long base = (long)wrow * 64;
    Hi[base + lane]      = h0;
    Hi[base + lane + 32] = h1;
    Lo[base + lane]      = __float2bfloat16(o0 - __bfloat162float(h0));
    Lo[base + lane + 32] = __float2bfloat16(o1 - __bfloat162float(h1));
}

// ---------------------------------------------------------------------------
// softmax over 2048 (key dim), scale 1/8; fp32 in, bf16 hi/lo out.
// One 256-thread block per row.
// ---------------------------------------------------------------------------
__global__ __launch_bounds__(256)
void softmax2048_kernel(const float* __restrict__ X, __nv_bfloat16* __restrict__ Hi,
                        __nv_bfloat16* __restrict__ Lo)
{
    const float* p = X + (long)blockIdx.x * 2048;
    int tid = threadIdx.x, lane = tid & 31, wid = tid >> 5;
    __shared__ float red[8];

    float v[8];
    float m = -3.4e38f;
#pragma unroll
    for (int i = 0; i < 8; i++) { v[i] = p[tid + 256 * i] * 0.125f; m = fmaxf(m, v[i]); }
#pragma unroll
    for (int o = 16; o; o >>= 1) m = fmaxf(m, __shfl_xor_sync(0xffffffffu, m, o));
    if (lane == 0) red[wid] = m;
    __syncthreads();
    float mm = red[0];
#pragma unroll
    for (int w = 1; w < 8; w++) mm = fmaxf(mm, red[w]);

    float s = 0.f;
#pragma unroll
    for (int i = 0; i < 8; i++) { v[i] = __expf(v[i] - mm); s += v[i]; }
#pragma unroll
    for (int o = 16; o; o >>= 1) s += __shfl_xor_sync(0xffffffffu, s, o);
    __syncthreads();
    if (lane == 0) red[wid] = s;
    __syncthreads();
    float ss = 0.f;
#pragma unroll
    for (int w = 0; w < 8; w++) ss += red[w];
    float inv = 1.0f / ss;

    long base = (long)blockIdx.x * 2048;
#pragma unroll
    for (int i = 0; i < 8; i++) {
        float f = v[i] * inv;
        __nv_bfloat16 h = __float2bfloat16(f);
        Hi[base + tid + 256 * i] = h;
        Lo[base + tid + 256 * i] = __float2bfloat16(f - __bfloat162float(h));
    }
}

// ---------------------------------------------------------------------------
// Launch pipeline. Inputs: query, key, value, Wv, bv, Wl, bl, Wo, bo
// ---------------------------------------------------------------------------
extern "C" void kernel_launch(void* const* d_in, const int* in_sizes, int n_in,
                              void* d_out, int out_size)
{
    const float* query = (const float*)d_in[0];
    const float* key   = (const float*)d_in[1];
    const float* value = (const float*)d_in[2];
    const float* Wv    = (const float*)d_in[3];
    const float* bv    = (const float*)d_in[4];
    const float* Wl    = (const float*)d_in[5];
    const float* bl    = (const float*)d_in[6];
    const float* Wo    = (const float*)d_in[7];
    const float* bo    = (const float*)d_in[8];
    float* out = (float*)d_out;
    (void)in_sizes; (void)n_in; (void)out_size;

    __nv_bfloat16 *Wv_hi, *Wv_lo, *Wo_hi, *Wo_lo, *Wl_hi, *Wl_lo;
    __nv_bfloat16 *val_hi, *val_lo, *q_hi, *q_lo, *k_hi, *k_lo;
    __nv_bfloat16 *vpT_hi, *vpT_lo, *ql_hi, *ql_lo, *kl_hi, *kl_lo;
    __nv_bfloat16 *attn_hi, *attn_lo, *out2_hi, *out2_lo;
    float *qlf, *klf, *attnf;
    cudaGetSymbolAddress((void**)&Wv_hi,  g_Wv_hi);  cudaGetSymbolAddress((void**)&Wv_lo,  g_Wv_lo);
    cudaGetSymbolAddress((void**)&Wo_hi,  g_Wo_hi);  cudaGetSymbolAddress((void**)&Wo_lo,  g_Wo_lo);
    cudaGetSymbolAddress((void**)&Wl_hi,  g_Wl_hi);  cudaGetSymbolAddress((void**)&Wl_lo,  g_Wl_lo);
    cudaGetSymbolAddress((void**)&val_hi, g_val_hi); cudaGetSymbolAddress((void**)&val_lo, g_val_lo);
    cudaGetSymbolAddress((void**)&q_hi,   g_q_hi);   cudaGetSymbolAddress((void**)&q_lo,   g_q_lo);
    cudaGetSymbolAddress((void**)&k_hi,   g_k_hi);   cudaGetSymbolAddress((void**)&k_lo,   g_k_lo);
    cudaGetSymbolAddress((void**)&vpT_hi, g_vpT_hi); cudaGetSymbolAddress((void**)&vpT_lo, g_vpT_lo);
    cudaGetSymbolAddress((void**)&ql_hi,  g_ql_hi);  cudaGetSymbolAddress((void**)&ql_lo,  g_ql_lo);
    cudaGetSymbolAddress((void**)&kl_hi,  g_kl_hi);  cudaGetSymbolAddress((void**)&kl_lo,  g_kl_lo);
    cudaGetSymbolAddress((void**)&attn_hi, g_attn_hi); cudaGetSymbolAddress((void**)&attn_lo, g_attn_lo);
    cudaGetSymbolAddress((void**)&out2_hi, g_out2_hi); cudaGetSymbolAddress((void**)&out2_lo, g_out2_lo);
    cudaGetSymbolAddress((void**)&qlf,   g_qlf);
    cudaGetSymbolAddress((void**)&klf,   g_klf);
    cudaGetSymbolAddress((void**)&attnf, g_attn);

    dim3 blk(256);

    // 0) split input operands into bf16 hi/lo
    auto split = [&](const float* src, __nv_bfloat16* hi, __nv_bfloat16* lo, long n) {
        int n4 = (int)(n / 4);
        split_kernel<<<(n4 + 255) / 256, blk>>>((const float4*)src, (uint2*)hi, (uint2*)lo, n4);
    };
    split(Wv,    Wv_hi,  Wv_lo,  (long)EMB * EMB);
    split(Wo,    Wo_hi,  Wo_lo,  (long)EMB * EMB);
    split(Wl,    Wl_hi,  Wl_lo,  (long)MLM * EMB);
    split(value, val_hi, val_lo, (long)NTOK * EMB);
    split(query, q_hi,   q_lo,   (long)NTOK * EMB);
    split(key,   k_hi,   k_lo,   (long)NTOK * EMB);

    // 1) VprojT[b,e,k] = sum_c Wv[e,c]*value[b,k,c] + bv[e]  -> bf16 hi/lo
    gemm_tc_kernel<<<dim3(LSEQ / TN, EMB / TM, BATCH), blk>>>(
        Wv_hi, Wv_lo, val_hi, val_lo, nullptr, vpT_hi, vpT_lo,
        EMB, LSEQ, EMB, 0L, (long)LSEQ * EMB, (long)EMB * LSEQ, bv, nullptr);

    // 2) landmark logits: [NTOK x 64] fp32
    gemm_tc_kernel<<<dim3(1, NTOK / TM, 1), blk>>>(
        q_hi, q_lo, Wl_hi, Wl_lo, qlf, nullptr, nullptr,
        NTOK, MLM, EMB, 0L, 0L, 0L, nullptr, bl);
    gemm_tc_kernel<<<dim3(1, NTOK / TM, 1), blk>>>(
        k_hi, k_lo, Wl_hi, Wl_lo, klf, nullptr, nullptr,
        NTOK, MLM, EMB, 0L, 0L, 0L, nullptr, bl);

    // 3) softmax over landmarks -> bf16 hi/lo
    softmax64_kernel<<<NTOK / 8, blk>>>(qlf, ql_hi, ql_lo, NTOK);
    softmax64_kernel<<<NTOK / 8, blk>>>(klf, kl_hi, kl_lo, NTOK);

    // 4) scores S[b,q,k] = ql . kl  (K=64) -> fp32
    gemm_tc_kernel<<<dim3(LSEQ / TN, LSEQ / TM, BATCH), blk>>>(
        ql_hi, ql_lo, kl_hi, kl_lo, attnf, nullptr, nullptr,
        LSEQ, LSEQ, MLM, (long)LSEQ * MLM, (long)LSEQ * MLM, (long)LSEQ * LSEQ,
        nullptr, nullptr);

    // 5) softmax over keys -> bf16 hi/lo
    softmax2048_kernel<<<NTOK, blk>>>(attnf, attn_hi, attn_lo);

    // 6) out2[b,q,e] = sum_k attn[b,q,k]*vprojT[b,e,k]  -> bf16 hi/lo
    gemm_tc_kernel<<<dim3(EMB / TN, LSEQ / TM, BATCH), blk>>>(
        attn_hi, attn_lo, vpT_hi, vpT_lo, nullptr, out2_hi, out2_lo,
        LSEQ, EMB, LSEQ, (long)LSEQ * LSEQ, (long)EMB * LSEQ, (long)LSEQ * EMB,
        nullptr, nullptr);

    // 7) out = out2 @ Wo^T + bo  -> fp32 d_out
    gemm_tc_kernel<<<dim3(EMB / TN, NTOK / TM, 1), blk>>>(
        out2_hi, out2_lo, Wo_hi, Wo_lo, out, nullptr, nullptr,
        NTOK, EMB, EMB, 0L, 0L, 0L, nullptr, bo);
}

// round 12
// speedup vs baseline: 2.3954x; 1.2714x over previous
#include <cuda_runtime.h>
#include <cuda_bf16.h>
#include <stdint.h>

// Problem constants: B=2, L=2048, E=1024, M_LM=64
#define BATCH 2
#define LSEQ  2048
#define EMB   1024
#define MLM   64
#define NTOK  (BATCH * LSEQ)   // 4096

// GEMM tile config
#define TM 128
#define TN 128
#define KC 32          // bf16 K elements per smem chunk
#define GT 256         // threads per GEMM CTA
#define ROWB 80        // smem bytes per row (32 bf16 = 64B + 16B pad, 16B aligned)
#define TILEB (128 * ROWB)       // 10240 B per tile
#define STAGEB (4 * TILEB)       // Ah, Al, Bh, Bl = 40960 B per stage
#define SMEM_TOTAL (2 * STAGEB)  // 81920 B (2-stage double buffer)

// ---------------- device scratch (no allocations anywhere) ----------------
__device__ __nv_bfloat16 g_Wv_hi[EMB * EMB],   g_Wv_lo[EMB * EMB];
__device__ __nv_bfloat16 g_Wo_hi[EMB * EMB],   g_Wo_lo[EMB * EMB];
__device__ __nv_bfloat16 g_Wl_hi[MLM * EMB],   g_Wl_lo[MLM * EMB];
__device__ __nv_bfloat16 g_val_hi[NTOK * EMB], g_val_lo[NTOK * EMB];
__device__ __nv_bfloat16 g_qk_hi[2 * NTOK * EMB], g_qk_lo[2 * NTOK * EMB]; // q | k
__device__ __nv_bfloat16 g_vpT_hi[(long)BATCH * EMB * LSEQ], g_vpT_lo[(long)BATCH * EMB * LSEQ];
__device__ float         g_qklf[2 * NTOK * MLM];                           // ql | kl logits
__device__ __nv_bfloat16 g_qkl_hi[2 * NTOK * MLM], g_qkl_lo[2 * NTOK * MLM];
__device__ float         g_attn[(long)BATCH * LSEQ * LSEQ];
__device__ __nv_bfloat16 g_attn_hi[(long)BATCH * LSEQ * LSEQ], g_attn_lo[(long)BATCH * LSEQ * LSEQ];
__device__ __nv_bfloat16 g_out2_hi[NTOK * EMB], g_out2_lo[NTOK * EMB];

// ---------------- helpers ----------------
__device__ __forceinline__ uint32_t smem_u32(const void* p) {
    uint32_t a;
    asm("{ .reg .u64 t; cvta.to.shared.u64 t, %1; cvt.u32.u64 %0, t; }" : "=r"(a) : "l"(p));
    return a;
}
__device__ __forceinline__ void ldsm4(uint32_t* r, uint32_t addr) {
    asm volatile("ldmatrix.sync.aligned.m8n8.x4.shared.b16 {%0,%1,%2,%3}, [%4];"
                 : "=r"(r[0]), "=r"(r[1]), "=r"(r[2]), "=r"(r[3]) : "r"(addr));
}
__device__ __forceinline__ void mma_bf16(float* c, const uint32_t* a,
                                         uint32_t b0, uint32_t b1) {
    asm volatile(
        "mma.sync.aligned.m16n8k16.row.col.f32.bf16.bf16.f32 "
        "{%0,%1,%2,%3}, {%4,%5,%6,%7}, {%8,%9}, {%0,%1,%2,%3};"
        : "+f"(c[0]), "+f"(c[1]), "+f"(c[2]), "+f"(c[3])
        : "r"(a[0]), "r"(a[1]), "r"(a[2]), "r"(a[3]), "r"(b0), "r"(b1));
}
__device__ __forceinline__ void cp_async16(uint32_t dst, const void* src, int srcsize) {
    asm volatile("cp.async.cg.shared.global [%0], [%1], 16, %2;"
                 :: "r"(dst), "l"(src), "r"(srcsize) : "memory");
}
__device__ __forceinline__ void cp_commit() {
    asm volatile("cp.async.commit_group;" ::: "memory");
}
__device__ __forceinline__ void cp_wait0() {
    asm volatile("cp.async.wait_group 0;" ::: "memory");
}
__device__ __forceinline__ uint32_t pack_bf(float a, float b) {
    __nv_bfloat16 ha = __float2bfloat16(a), hb = __float2bfloat16(b);
    return (uint32_t)__bfloat16_as_ushort(ha) | ((uint32_t)__bfloat16_as_ushort(hb) << 16);
}

// ---------------------------------------------------------------------------
// bf16-split NT GEMM on HMMA (mma.sync m16n8k16), cp.async double-buffered:
//   C[m,n] = sum_k (Ahi+Alo)[m,k]*(Bhi+Blo)[n,k]   (3-term split, fp32 accum)
// A*: [M x K] bf16 row-major, B*: [N x K] bf16 row-major.
// Output: Cf != null -> fp32 (+biases); else bf16 hi/lo split pair.
// Requires K % 32 == 0, rows 16B-aligned. M,N tiles padded by zero-fill.
// 128x128 CTA tile, 256 threads = 8 warps (2 x 4), warp tile 64x32.
// ---------------------------------------------------------------------------
__global__ __launch_bounds__(GT, 2)
void gemm_tc_kernel(const __nv_bfloat16* __restrict__ Ahi, const __nv_bfloat16* __restrict__ Alo,
                    const __nv_bfloat16* __restrict__ Bhi, const __nv_bfloat16* __restrict__ Blo,
                    float* __restrict__ Cf,
                    __nv_bfloat16* __restrict__ Chi, __nv_bfloat16* __restrict__ Clo,
                    int M, int N, int K,
                    long sA, long sB, long sC,
                    const float* __restrict__ bias_m, const float* __restrict__ bias_n)
{
    extern __shared__ __align__(16) char smem[];

    const int tid  = threadIdx.x;
    const int wid  = tid >> 5;
    const int lane = tid & 31;
    const int wm   = wid >> 2;       // 0..1  (64-row half)
    const int wn   = wid & 3;        // 0..3  (32-col quarter)
    const uint32_t sb = smem_u32(smem);

    const long bz = blockIdx.z;
    Ahi += bz * sA;  Alo += bz * sA;
    Bhi += bz * sB;  Blo += bz * sB;
    if (Cf) Cf += bz * sC; else { Chi += bz * sC; Clo += bz * sC; }

    const int m0 = blockIdx.y * TM;
    const int n0 = blockIdx.x * TN;

    float acc[4][4][4];
#pragma unroll
    for (int i = 0; i < 4; i++)
#pragma unroll
        for (int j = 0; j < 4; j++)
#pragma unroll
            for (int r = 0; r < 4; r++) acc[i][j][r] = 0.f;

    // cp.async tile loader: 128 rows x 32 bf16 (64B/row) -> 80B smem rows.
    // 512 16B-segments per tile, 2 per thread; OOB rows zero-filled (srcsize=0).
    auto load_chunk = [&](int kt, uint32_t stage_off) {
#pragma unroll
        for (int it = 0; it < 2; it++) {
            int id  = tid + GT * it;       // 0..511
            int row = id >> 2;
            int seg = id & 3;              // 16B segment
            uint32_t doff = stage_off + row * ROWB + seg * 16;
            // A tiles
            {
                int gr = m0 + row;
                int ok = (gr < M) ? 16 : 0;
                int cg = ok ? gr : (M - 1);
                const char* pah = (const char*)(Ahi + (long)cg * K + kt) + seg * 16;
                cp_async16(sb + doff, pah, ok);
                const char* pal = (const char*)(Alo + (long)cg * K + kt) + seg * 16;
                cp_async16(sb + doff + TILEB, pal, ok);
            }
            // B tiles
            {
                int gr = n0 + row;
                int ok = (gr < N) ? 16 : 0;
                int cg = ok ? gr : (N - 1);
                const char* pbh = (const char*)(Bhi + (long)cg * K + kt) + seg * 16;
                cp_async16(sb + doff + 2 * TILEB, pbh, ok);
                const char* pbl = (const char*)(Blo + (long)cg * K + kt) + seg * 16;
                cp_async16(sb + doff + 3 * TILEB, pbl, ok);
            }
        }
    };

    // ldmatrix lane addressing: row offset lane&15, k-half byte offset lane>>4
    const int lrow = (lane & 15);
    const int lcol = ((lane >> 4) << 3) * 2;   // 0 or 16 bytes

    const int nchunks = K / KC;
    load_chunk(0, 0);
    cp_commit();

    int stage = 0;
    for (int c = 0; c < nchunks; c++) {
        cp_wait0();
        __syncthreads();

        if (c + 1 < nchunks) {
            load_chunk((c + 1) * KC, (stage ^ 1) * STAGEB);
            cp_commit();
        }

        const uint32_t sAh = sb + stage * STAGEB;
        const uint32_t sAl = sAh + TILEB;
        const uint32_t sBh = sAh + 2 * TILEB;
        const uint32_t sBl = sAh + 3 * TILEB;

#pragma unroll
        for (int ks = 0; ks < 2; ks++) {
            const uint32_t kb = ks * 32 + lcol;    // byte offset within row

            // A_hi fragments: 4 x (16x16)
            uint32_t ah[4][4];
#pragma unroll
            for (int mi = 0; mi < 4; mi++)
                ldsm4(ah[mi], sAh + (uint32_t)(wm * 64 + mi * 16 + lrow) * ROWB + kb);

            // B_hi fragments: 2 x ldmatrix.x4 -> 4 n-frags of (8x16)
            uint32_t bh[4][2];
#pragma unroll
            for (int nb = 0; nb < 2; nb++) {
                uint32_t t[4];
                ldsm4(t, sBh + (uint32_t)(wn * 32 + nb * 16 + lrow) * ROWB + kb);
                bh[nb * 2 + 0][0] = t[0]; bh[nb * 2 + 0][1] = t[2];
                bh[nb * 2 + 1][0] = t[1]; bh[nb * 2 + 1][1] = t[3];
            }

            // hi * hi
#pragma unroll
            for (int mi = 0; mi < 4; mi++)
#pragma unroll
                for (int f = 0; f < 4; f++)
                    mma_bf16(acc[mi][f], ah[mi], bh[f][0], bh[f][1]);

            // lo * hi (stream A_lo one fragment at a time)
#pragma unroll
            for (int mi = 0; mi < 4; mi++) {
                uint32_t al[4];
                ldsm4(al, sAl + (uint32_t)(wm * 64 + mi * 16 + lrow) * ROWB + kb);
#pragma unroll
                for (int f = 0; f < 4; f++)
                    mma_bf16(acc[mi][f], al, bh[f][0], bh[f][1]);
            }

            // hi * lo (stream B_lo)
#pragma unroll
            for (int nb = 0; nb < 2; nb++) {
                uint32_t t[4];
                ldsm4(t, sBl + (uint32_t)(wn * 32 + nb * 16 + lrow) * ROWB + kb);
#pragma unroll
                for (int mi = 0; mi < 4; mi++) {
                    mma_bf16(acc[mi][nb * 2 + 0], ah[mi], t[0], t[2]);
                    mma_bf16(acc[mi][nb * 2 + 1], ah[mi], t[1], t[3]);
                }
            }
        }
        stage ^= 1;
        __syncthreads();
    }

    // Epilogue. c0,c1 -> row lane>>2, cols (lane&3)*2 +{0,1}; c2,c3 -> row+8.
    const int rbase = m0 + wm * 64 + (lane >> 2);
    const int cbase = n0 + wn * 32 + (lane & 3) * 2;
#pragma unroll
    for (int mi = 0; mi < 4; mi++) {
#pragma unroll
        for (int half = 0; half < 2; half++) {
            int m = rbase + mi * 16 + half * 8;
            if (m >= M) continue;
            float bm = bias_m ? bias_m[m] : 0.f;
#pragma unroll
            for (int f = 0; f < 4; f++) {
                int n = cbase + f * 8;
                if (n >= N) continue;
                float f0 = acc[mi][f][half * 2 + 0] + bm + (bias_n ? bias_n[n] : 0.f);
                float f1 = acc[mi][f][half * 2 + 1] + bm + (bias_n ? bias_n[n + 1] : 0.f);
                long o = (long)m * N + n;
                if (Cf) {
                    *reinterpret_cast<float2*>(Cf + o) = make_float2(f0, f1);
                } else {
                    __nv_bfloat16 h0 = __float2bfloat16(f0), h1 = __float2bfloat16(f1);
                    uint32_t hv = (uint32_t)__bfloat16_as_ushort(h0) |
                                  ((uint32_t)__bfloat16_as_ushort(h1) << 16);
                    uint32_t lv = pack_bf(f0 - __bfloat162float(h0), f1 - __bfloat162float(h1));
                    *reinterpret_cast<uint32_t*>(Chi + o) = hv;
                    *reinterpret_cast<uint32_t*>(Clo + o) = lv;
                }
            }
        }
    }
}

// ---------------------------------------------------------------------------
// fp32 -> (hi, lo) bf16 split, vectorized float4
// ---------------------------------------------------------------------------
__global__ __launch_bounds__(256)
void split_kernel(const float4* __restrict__ x, uint2* __restrict__ hi,
                  uint2* __restrict__ lo, int n4)
{
    int i = blockIdx.x * 256 + threadIdx.x;
    if (i >= n4) return;
    float4 v = x[i];
    __nv_bfloat16 h0 = __float2bfloat16(v.x), h1 = __float2bfloat16(v.y);
    __nv_bfloat16 h2 = __float2bfloat16(v.z), h3 = __float2bfloat16(v.w);
    uint2 hv, lv;
    hv.x = (uint32_t)__bfloat16_as_ushort(h0) | ((uint32_t)__bfloat16_as_ushort(h1) << 16);
    hv.y = (uint32_t)__bfloat16_as_ushort(h2) | ((uint32_t)__bfloat16_as_ushort(h3) << 16);
    lv.x = pack_bf(v.x - __bfloat162float(h0), v.y - __bfloat162float(h1));
    lv.y = pack_bf(v.z - __bfloat162float(h2), v.w - __bfloat162float(h3));
    hi[i] = hv;
    lo[i] = lv;
}

// ---------------------------------------------------------------------------
// softmax over 64 (landmark dim), scale 1/8; fp32 in, bf16 hi/lo out.
// One warp per row.
// ---------------------------------------------------------------------------
__global__ __launch_bounds__(256)
void softmax64_kernel(const float* __restrict__ X, __nv_bfloat16* __restrict__ Hi,
                      __nv_bfloat16* __restrict__ Lo, int rows)
{
    int wrow = (blockIdx.x * blockDim.x + threadIdx.x) >> 5;
    int lane = threadIdx.x & 31;
    if (wrow >= rows) return;
    const float* p = X + (long)wrow * 64;
    float v0 = p[lane] * 0.125f;
    float v1 = p[lane + 32] * 0.125f;
    float m = fmaxf(v0, v1);
#pragma unroll
    for (int o = 16; o; o >>= 1) m = fmaxf(m, __shfl_xor_sync(0xffffffffu, m, o));
    float e0 = __expf(v0 - m), e1 = __expf(v1 - m);
    float s = e0 + e1;
#pragma unroll
    for (int o = 16; o; o >>= 1) s += __shfl_xor_sync(0xffffffffu, s, o);
    float inv = 1.0f / s;
    float o0 = e0 * inv, o1 = e1 * inv;
    __nv_bfloat16 h0 = __float2bfloat16(o0), h1 = __float2bfloat16(o1);
    long base = (long)wrow * 64;
    Hi[base + lane]      = h0;
    Hi[base + lane + 32] = h1;
    Lo[base + lane]      = __float2bfloat16(o0 - __bfloat162float(h0));
    Lo[base + lane + 32] = __float2bfloat16(o1 - __bfloat162float(h1));
}

// ---------------------------------------------------------------------------
// softmax over 2048 (key dim), scale 1/8; fp32 in, bf16 hi/lo out.
// One 256-thread block per row.
// ---------------------------------------------------------------------------
__global__ __launch_bounds__(256)
void softmax2048_kernel(const float* __restrict__ X, __nv_bfloat16* __restrict__ Hi,
                        __nv_bfloat16* __restrict__ Lo)
{
    const float* p = X + (long)blockIdx.x * 2048;
    int tid = threadIdx.x, lane = tid & 31, wid = tid >> 5;
    __shared__ float red[8];

    float v[8];
    float m = -3.4e38f;
#pragma unroll
    for (int i = 0; i < 8; i++) { v[i] = p[tid + 256 * i] * 0.125f; m = fmaxf(m, v[i]); }
#pragma unroll
    for (int o = 16; o; o >>= 1) m = fmaxf(m, __shfl_xor_sync(0xffffffffu, m, o));
    if (lane == 0) red[wid] = m;
    __syncthreads();
    float mm = red[0];
#pragma unroll
    for (int w = 1; w < 8; w++) mm = fmaxf(mm, red[w]);

    float s = 0.f;
#pragma unroll
    for (int i = 0; i < 8; i++) { v[i] = __expf(v[i] - mm); s += v[i]; }
#pragma unroll
    for (int o = 16; o; o >>= 1) s += __shfl_xor_sync(0xffffffffu, s, o);
    __syncthreads();
    if (lane == 0) red[wid] = s;
    __syncthreads();
    float ss = 0.f;
#pragma unroll
    for (int w = 0; w < 8; w++) ss += red[w];
    float inv = 1.0f / ss;

    long base = (long)blockIdx.x * 2048;
#pragma unroll
    for (int i = 0; i < 8; i++) {
        float f = v[i] * inv;
        __nv_bfloat16 h = __float2bfloat16(f);
        Hi[base + tid + 256 * i] = h;
        Lo[base + tid + 256 * i] = __float2bfloat16(f - __bfloat162float(h));
    }
}

// ---------------------------------------------------------------------------
// Launch pipeline. Inputs: query, key, value, Wv, bv, Wl, bl, Wo, bo
// ---------------------------------------------------------------------------
extern "C" void kernel_launch(void* const* d_in, const int* in_sizes, int n_in,
                              void* d_out, int out_size)
{
    const float* query = (const float*)d_in[0];
    const float* key   = (const float*)d_in[1];
    const float* value = (const float*)d_in[2];
    const float* Wv    = (const float*)d_in[3];
    const float* bv    = (const float*)d_in[4];
    const float* Wl    = (const float*)d_in[5];
    const float* bl    = (const float*)d_in[6];
    const float* Wo    = (const float*)d_in[7];
    const float* bo    = (const float*)d_in[8];
    float* out = (float*)d_out;
    (void)in_sizes; (void)n_in; (void)out_size;

    // Unconditional (no static guards — harness rule). Idempotent host-side call.
    cudaFuncSetAttribute(gemm_tc_kernel,
                         cudaFuncAttributeMaxDynamicSharedMemorySize, SMEM_TOTAL);

    __nv_bfloat16 *Wv_hi, *Wv_lo, *Wo_hi, *Wo_lo, *Wl_hi, *Wl_lo;
    __nv_bfloat16 *val_hi, *val_lo, *qk_hi, *qk_lo;
    __nv_bfloat16 *vpT_hi, *vpT_lo, *qkl_hi, *qkl_lo;
    __nv_bfloat16 *attn_hi, *attn_lo, *out2_hi, *out2_lo;
    float *qklf, *attnf;
    cudaGetSymbolAddress((void**)&Wv_hi,  g_Wv_hi);  cudaGetSymbolAddress((void**)&Wv_lo,  g_Wv_lo);
    cudaGetSymbolAddress((void**)&Wo_hi,  g_Wo_hi);  cudaGetSymbolAddress((void**)&Wo_lo,  g_Wo_lo);
    cudaGetSymbolAddress((void**)&Wl_hi,  g_Wl_hi);  cudaGetSymbolAddress((void**)&Wl_lo,  g_Wl_lo);
    cudaGetSymbolAddress((void**)&val_hi, g_val_hi); cudaGetSymbolAddress((void**)&val_lo, g_val_lo);
    cudaGetSymbolAddress((void**)&qk_hi,  g_qk_hi);  cudaGetSymbolAddress((void**)&qk_lo,  g_qk_lo);
    cudaGetSymbolAddress((void**)&vpT_hi, g_vpT_hi); cudaGetSymbolAddress((void**)&vpT_lo, g_vpT_lo);
    cudaGetSymbolAddress((void**)&qkl_hi, g_qkl_hi); cudaGetSymbolAddress((void**)&qkl_lo, g_qkl_lo);
    cudaGetSymbolAddress((void**)&attn_hi, g_attn_hi); cudaGetSymbolAddress((void**)&attn_lo, g_attn_lo);
    cudaGetSymbolAddress((void**)&out2_hi, g_out2_hi); cudaGetSymbolAddress((void**)&out2_lo, g_out2_lo);
    cudaGetSymbolAddress((void**)&qklf,  g_qklf);
    cudaGetSymbolAddress((void**)&attnf, g_attn);

    dim3 blk(256);

    // 0) split input operands into bf16 hi/lo (q and k into contiguous halves)
    auto split = [&](const float* src, __nv_bfloat16* hi, __nv_bfloat16* lo, long n) {
        int n4 = (int)(n / 4);
        split_kernel<<<(n4 + 255) / 256, blk>>>((const float4*)src, (uint2*)hi, (uint2*)lo, n4);
    };
    split(Wv,    Wv_hi,  Wv_lo,  (long)EMB * EMB);
    split(Wo,    Wo_hi,  Wo_lo,  (long)EMB * EMB);
    split(Wl,    Wl_hi,  Wl_lo,  (long)MLM * EMB);
    split(value, val_hi, val_lo, (long)NTOK * EMB);
    split(query, qk_hi,                    qk_lo,                    (long)NTOK * EMB);
    split(key,   qk_hi + (long)NTOK * EMB, qk_lo + (long)NTOK * EMB, (long)NTOK * EMB);

    // 1) VprojT[b,e,k] = sum_c Wv[e,c]*value[b,k,c] + bv[e]  -> bf16 hi/lo
    gemm_tc_kernel<<<dim3(LSEQ / TN, EMB / TM, BATCH), blk, SMEM_TOTAL>>>(
        Wv_hi, Wv_lo, val_hi, val_lo, nullptr, vpT_hi, vpT_lo,
        EMB, LSEQ, EMB, 0L, (long)LSEQ * EMB, (long)EMB * LSEQ, bv, nullptr);

    // 2) landmark logits for q and k together: [2*NTOK x 64] fp32
    gemm_tc_kernel<<<dim3(1, 2 * NTOK / TM, 1), blk, SMEM_TOTAL>>>(
        qk_hi, qk_lo, Wl_hi, Wl_lo, qklf, nullptr, nullptr,
        2 * NTOK, MLM, EMB, 0L, 0L, 0L, nullptr, bl);

    // 3) softmax over landmarks -> bf16 hi/lo (q rows then k rows)
    softmax64_kernel<<<2 * NTOK / 8, blk>>>(qklf, qkl_hi, qkl_lo, 2 * NTOK);

    // 4) scores S[b,q,k] = ql . kl  (K=64) -> fp32
    gemm_tc_kernel<<<dim3(LSEQ / TN, LSEQ / TM, BATCH), blk, SMEM_TOTAL>>>(
        qkl_hi, qkl_lo,
        qkl_hi + (long)NTOK * MLM, qkl_lo + (long)NTOK * MLM,
        attnf, nullptr, nullptr,
        LSEQ, LSEQ, MLM, (long)LSEQ * MLM, (long)LSEQ * MLM, (long)LSEQ * LSEQ,
        nullptr, nullptr);

    // 5) softmax over keys -> bf16 hi/lo
    softmax2048_kernel<<<NTOK, blk>>>(attnf, attn_hi, attn_lo);

    // 6) out2[b,q,e] = sum_k attn[b,q,k]*vprojT[b,e,k]  -> bf16 hi/lo
    gemm_tc_kernel<<<dim3(EMB / TN, LSEQ / TM, BATCH), blk, SMEM_TOTAL>>>(
        attn_hi, attn_lo, vpT_hi, vpT_lo, nullptr, out2_hi, out2_lo,
        LSEQ, EMB, LSEQ, (long)LSEQ * LSEQ, (long)EMB * LSEQ, (long)LSEQ * EMB,
        nullptr, nullptr);

    // 7) out = out2 @ Wo^T + bo  -> fp32 d_out
    gemm_tc_kernel<<<dim3(EMB / TN, NTOK / TM, 1), blk, SMEM_TOTAL>>>(
        out2_hi, out2_lo, Wo_hi, Wo_lo, out, nullptr, nullptr,
        NTOK, EMB, EMB, 0L, 0L, 0L, nullptr, bo);
}

// round 13
// speedup vs baseline: 3.0864x; 1.2884x over previous
#include <cuda_runtime.h>
#include <cuda.h>
#include <cuda_bf16.h>
#include <stdint.h>

// Problem constants: B=2, L=2048, E=1024, M_LM=64
#define BATCH 2
#define LSEQ  2048
#define EMB   1024
#define MLM   64
#define NTOK  (BATCH * LSEQ)   // 4096

// GEMM tile config
#define TM 128
#define TN 128
#define KC 32                    // bf16 K elems per chunk (64B row, SW64)
#define GT 256                   // threads per GEMM CTA
#define TILE2 8192               // 128 rows x 64 B
#define STAGE2 (4 * TILE2)       // Ah, Al, Bh, Bl = 32768 B
#define SMEM_TOTAL (1024 + 2 * STAGE2)   // 66560 B

// ---------------- device scratch (no allocations anywhere) ----------------
__device__ __nv_bfloat16 g_Wv_hi[EMB * EMB],   g_Wv_lo[EMB * EMB];
__device__ __nv_bfloat16 g_Wo_hi[EMB * EMB],   g_Wo_lo[EMB * EMB];
__device__ __nv_bfloat16 g_Wl_hi[MLM * EMB],   g_Wl_lo[MLM * EMB];
__device__ __nv_bfloat16 g_val_hi[NTOK * EMB], g_val_lo[NTOK * EMB];
__device__ __nv_bfloat16 g_qk_hi[2 * NTOK * EMB], g_qk_lo[2 * NTOK * EMB]; // q | k
__device__ __nv_bfloat16 g_vpT_hi[(long)BATCH * EMB * LSEQ], g_vpT_lo[(long)BATCH * EMB * LSEQ];
__device__ __nv_bfloat16 g_qkl_hi[2 * NTOK * MLM], g_qkl_lo[2 * NTOK * MLM]; // ql | kl (post-softmax)
__device__ float         g_attn[(long)BATCH * LSEQ * LSEQ];
__device__ __nv_bfloat16 g_attn_hi[(long)BATCH * LSEQ * LSEQ], g_attn_lo[(long)BATCH * LSEQ * LSEQ];
__device__ __nv_bfloat16 g_out2_hi[NTOK * EMB], g_out2_lo[NTOK * EMB];

// ---------------- device helpers ----------------
__device__ __forceinline__ uint32_t smem_u32(const void* p) {
    uint32_t a;
    asm("{ .reg .u64 t; cvta.to.shared.u64 t, %1; cvt.u32.u64 %0, t; }" : "=r"(a) : "l"(p));
    return a;
}
__device__ __forceinline__ void ldsm4(uint32_t* r, uint32_t addr) {
    asm volatile("ldmatrix.sync.aligned.m8n8.x4.shared.b16 {%0,%1,%2,%3}, [%4];"
                 : "=r"(r[0]), "=r"(r[1]), "=r"(r[2]), "=r"(r[3]) : "r"(addr));
}
__device__ __forceinline__ void mma_bf16(float* c, const uint32_t* a,
                                         uint32_t b0, uint32_t b1) {
    asm volatile(
        "mma.sync.aligned.m16n8k16.row.col.f32.bf16.bf16.f32 "
        "{%0,%1,%2,%3}, {%4,%5,%6,%7}, {%8,%9}, {%0,%1,%2,%3};"
        : "+f"(c[0]), "+f"(c[1]), "+f"(c[2]), "+f"(c[3])
        : "r"(a[0]), "r"(a[1]), "r"(a[2]), "r"(a[3]), "r"(b0), "r"(b1));
}
__device__ __forceinline__ void mbar_init(uint32_t mb, uint32_t cnt) {
    asm volatile("mbarrier.init.shared.b64 [%0], %1;" :: "r"(mb), "r"(cnt) : "memory");
}
__device__ __forceinline__ void mbar_expect(uint32_t mb, uint32_t bytes) {
    asm volatile("mbarrier.arrive.expect_tx.shared.b64 _, [%0], %1;"
                 :: "r"(mb), "r"(bytes) : "memory");
}
__device__ __forceinline__ void mbar_wait(uint32_t mb, uint32_t parity) {
    asm volatile(
        "{\n\t.reg .pred P;\n"
        "LW%=:\n\tmbarrier.try_wait.parity.acquire.cta.shared::cta.b64 P, [%0], %1, 0x989680;\n\t"
        "@P bra LD%=;\n\tbra LW%=;\nLD%=:\n\t}"
        :: "r"(mb), "r"(parity) : "memory");
}
__device__ __forceinline__ void tma3d(uint32_t dst, const void* tmap,
                                      int x, int y, int z, uint32_t mb) {
    asm volatile(
        "cp.async.bulk.tensor.3d.shared::cta.global.tile.mbarrier::complete_tx::bytes "
        "[%0], [%1, {%2, %3, %4}], [%5];"
        :: "r"(dst), "l"(tmap), "r"(x), "r"(y), "r"(z), "r"(mb) : "memory");
}
__device__ __forceinline__ uint32_t pack_bf(float a, float b) {
    __nv_bfloat16 ha = __float2bfloat16(a), hb = __float2bfloat16(b);
    return (uint32_t)__bfloat16_as_ushort(ha) | ((uint32_t)__bfloat16_as_ushort(hb) << 16);
}
#define SWZ64(o) ((o) ^ (((o) >> 3) & 0x30))

// ---------------------------------------------------------------------------
// bf16-split NT GEMM, TMA-fed double-buffered, HMMA mma.sync m16n8k16:
//   C[m,n] = sum_k (Ahi+Alo)[m,k]*(Bhi+Blo)[n,k]   (3-term split, fp32 accum)
// Tiles arrive via cp.async.bulk.tensor (SW64 swizzle, 64B rows, OOB zero-fill).
// mode 0: fp32 out (+biases). mode 1: bf16 hi/lo split out.
// mode 2: N=64 landmark path — fused softmax over 64 cols (scale 1/8) then hi/lo.
// 128x128 CTA tile, 256 threads = 8 warps (2 x 4), warp tile 64x32.
// ---------------------------------------------------------------------------
__global__ __launch_bounds__(GT, 2)
void gemm_tma_kernel(const __grid_constant__ CUtensorMap tAh,
                     const __grid_constant__ CUtensorMap tAl,
                     const __grid_constant__ CUtensorMap tBh,
                     const __grid_constant__ CUtensorMap tBl,
                     float* __restrict__ Cf,
                     __nv_bfloat16* __restrict__ Chi, __nv_bfloat16* __restrict__ Clo,
                     int M, int N, int K, int zA, int zB, long sC,
                     const float* __restrict__ bias_m, const float* __restrict__ bias_n,
                     int mode)
{
    extern __shared__ __align__(1024) char smem[];

    const int tid  = threadIdx.x;
    const int wid  = tid >> 5;
    const int lane = tid & 31;
    const int wm   = wid >> 2;       // 0..1  (64-row half)
    const int wn   = wid & 3;        // 0..3  (32-col quarter)
    const uint32_t sb = smem_u32(smem);
    const int bz = blockIdx.z;

    if (mode == 0) Cf += (long)bz * sC; else { Chi += (long)bz * sC; Clo += (long)bz * sC; }

    const int m0 = blockIdx.y * TM;
    const int n0 = blockIdx.x * TN;
    const int za = zA ? bz : 0;
    const int zb = zB ? bz : 0;

    if (tid == 0) { mbar_init(sb, 1); mbar_init(sb + 8, 1); }
    __syncthreads();

    const int nch = K / KC;
    auto issue = [&](int c, int s) {
        uint32_t dst = sb + 1024 + s * STAGE2;
        uint32_t mb  = sb + s * 8;
        mbar_expect(mb, STAGE2);
        int kt = c * KC;
        tma3d(dst,             &tAh, kt, m0, za, mb);
        tma3d(dst + TILE2,     &tAl, kt, m0, za, mb);
        tma3d(dst + 2 * TILE2, &tBh, kt, n0, zb, mb);
        tma3d(dst + 3 * TILE2, &tBl, kt, n0, zb, mb);
    };
    if (tid == 0) { issue(0, 0); if (nch > 1) issue(1, 1); }

    float acc[4][4][4];
#pragma unroll
    for (int i = 0; i < 4; i++)
#pragma unroll
        for (int j = 0; j < 4; j++)
#pragma unroll
            for (int r = 0; r < 4; r++) acc[i][j][r] = 0.f;

    // ldmatrix lane addressing: row offset lane&15, k-half byte offset lane>>4
    const int lrow = (lane & 15);
    const int lcol = (lane >> 4) * 16;   // 0 or 16 bytes

    int ph0 = 0, ph1 = 0;
    for (int c = 0; c < nch; c++) {
        const int s = c & 1;
        if (s == 0) { mbar_wait(sb, ph0); ph0 ^= 1; }
        else        { mbar_wait(sb + 8, ph1); ph1 ^= 1; }

        const uint32_t sAh = sb + 1024 + s * STAGE2;
        const uint32_t sAl = sAh + TILE2;
        const uint32_t sBh = sAh + 2 * TILE2;
        const uint32_t sBl = sAh + 3 * TILE2;

#pragma unroll
        for (int ks = 0; ks < 2; ks++) {
            const uint32_t kb = ks * 32 + lcol;    // byte offset within 64B row

            // A_hi fragments: 4 x (16x16)
            uint32_t ah[4][4];
#pragma unroll
            for (int mi = 0; mi < 4; mi++) {
                uint32_t o = (uint32_t)(wm * 64 + mi * 16 + lrow) * 64 + kb;
                ldsm4(ah[mi], sAh + SWZ64(o));
            }

            // B_hi fragments: 2 x ldmatrix.x4 -> 4 n-frags of (8x16)
            uint32_t bh[4][2];
#pragma unroll
            for (int nb = 0; nb < 2; nb++) {
                uint32_t t[4];
                uint32_t o = (uint32_t)(wn * 32 + nb * 16 + lrow) * 64 + kb;
                ldsm4(t, sBh + SWZ64(o));
                bh[nb * 2 + 0][0] = t[0]; bh[nb * 2 + 0][1] = t[2];
                bh[nb * 2 + 1][0] = t[1]; bh[nb * 2 + 1][1] = t[3];
            }

            // hi * hi
#pragma unroll
            for (int mi = 0; mi < 4; mi++)
#pragma unroll
                for (int f = 0; f < 4; f++)
                    mma_bf16(acc[mi][f], ah[mi], bh[f][0], bh[f][1]);

            // lo * hi (stream A_lo)
#pragma unroll
            for (int mi = 0; mi < 4; mi++) {
                uint32_t al[4];
                uint32_t o = (uint32_t)(wm * 64 + mi * 16 + lrow) * 64 + kb;
                ldsm4(al, sAl + SWZ64(o));
#pragma unroll
                for (int f = 0; f < 4; f++)
                    mma_bf16(acc[mi][f], al, bh[f][0], bh[f][1]);
            }

            // hi * lo (stream B_lo)
#pragma unroll
            for (int nb = 0; nb < 2; nb++) {
                uint32_t t[4];
                uint32_t o = (uint32_t)(wn * 32 + nb * 16 + lrow) * 64 + kb;
                ldsm4(t, sBl + SWZ64(o));
#pragma unroll
                for (int mi = 0; mi < 4; mi++) {
                    mma_bf16(acc[mi][nb * 2 + 0], ah[mi], t[0], t[2]);
                    mma_bf16(acc[mi][nb * 2 + 1], ah[mi], t[1], t[3]);
                }
            }
        }
        __syncthreads();   // all warps done reading stage s
        if (tid == 0 && c + 2 < nch) issue(c + 2, s);
    }

    // ---------------- epilogues ----------------
    if (mode == 2) {
        // Fused softmax over 64 landmark cols. Stage fp32 tile (128 x 64) in smem.
        float* sred = (float*)(smem + 1024);   // [128][65]
#pragma unroll
        for (int mi = 0; mi < 4; mi++)
#pragma unroll
            for (int half = 0; half < 2; half++) {
                int ml = wm * 64 + mi * 16 + half * 8 + (lane >> 2);
#pragma unroll
                for (int f = 0; f < 4; f++) {
                    int n = wn * 32 + f * 8 + (lane & 3) * 2;
                    if (n < 64) {
                        sred[ml * 65 + n]     = acc[mi][f][half * 2 + 0] + bias_n[n];
                        sred[ml * 65 + n + 1] = acc[mi][f][half * 2 + 1] + bias_n[n + 1];
                    }
                }
            }
        __syncthreads();
        // one warp -> 16 rows
        for (int i = 0; i < 16; i++) {
            int r = wid * 16 + i;
            float v0 = sred[r * 65 + lane] * 0.125f;
            float v1 = sred[r * 65 + lane + 32] * 0.125f;
            float mx = fmaxf(v0, v1);
#pragma unroll
            for (int o = 16; o; o >>= 1) mx = fmaxf(mx, __shfl_xor_sync(0xffffffffu, mx, o));
            float e0 = __expf(v0 - mx), e1 = __expf(v1 - mx);
            float sm = e0 + e1;
#pragma unroll
            for (int o = 16; o; o >>= 1) sm += __shfl_xor_sync(0xffffffffu, sm, o);
            float inv = 1.0f / sm;
            float o0 = e0 * inv, o1 = e1 * inv;
            __nv_bfloat16 h0 = __float2bfloat16(o0), h1 = __float2bfloat16(o1);
            long base = (long)(m0 + r) * 64;
            Chi[base + lane]      = h0;
            Chi[base + lane + 32] = h1;
            Clo[base + lane]      = __float2bfloat16(o0 - __bfloat162float(h0));
            Clo[base + lane + 32] = __float2bfloat16(o1 - __bfloat162float(h1));
        }
        return;
    }

    const int rbase = m0 + wm * 64 + (lane >> 2);
    const int cbase = n0 + wn * 32 + (lane & 3) * 2;
#pragma unroll
    for (int mi = 0; mi < 4; mi++) {
#pragma unroll
        for (int half = 0; half < 2; half++) {
            int m = rbase + mi * 16 + half * 8;
            if (m >= M) continue;
            float bm = bias_m ? bias_m[m] : 0.f;
#pragma unroll
            for (int f = 0; f < 4; f++) {
                int n = cbase + f * 8;
                if (n >= N) continue;
                float f0 = acc[mi][f][half * 2 + 0] + bm + (bias_n ? bias_n[n] : 0.f);
                float f1 = acc[mi][f][half * 2 + 1] + bm + (bias_n ? bias_n[n + 1] : 0.f);
                long o = (long)m * N + n;
                if (mode == 0) {
                    *reinterpret_cast<float2*>(Cf + o) = make_float2(f0, f1);
                } else {
                    __nv_bfloat16 h0 = __float2bfloat16(f0), h1 = __float2bfloat16(f1);
                    uint32_t hv = (uint32_t)__bfloat16_as_ushort(h0) |
                                  ((uint32_t)__bfloat16_as_ushort(h1) << 16);
                    uint32_t lv = pack_bf(f0 - __bfloat162float(h0), f1 - __bfloat162float(h1));
                    *reinterpret_cast<uint32_t*>(Chi + o) = hv;
                    *reinterpret_cast<uint32_t*>(Clo + o) = lv;
                }
            }
        }
    }
}

// ---------------------------------------------------------------------------
// Fused fp32 -> bf16 hi/lo split for ALL six operands in one launch.
// Segment boundaries are compile-time constants (blocks of 256 thr x 1 float4).
// ---------------------------------------------------------------------------
#define N4_WV (EMB * EMB / 4)        // 262144 -> 1024 blocks
#define N4_WL (MLM * EMB / 4)        // 16384  -> 64 blocks
#define N4_X  (NTOK * EMB / 4)       // 1048576-> 4096 blocks
#define BL_WV (N4_WV / 256)
#define BL_WL (N4_WL / 256)
#define BL_X  (N4_X / 256)
#define SPLIT_BLOCKS (2 * BL_WV + BL_WL + 3 * BL_X)   // 14400

__global__ __launch_bounds__(256)
void split_all_kernel(const float4* __restrict__ Wv, const float4* __restrict__ Wo,
                      const float4* __restrict__ Wl, const float4* __restrict__ Val,
                      const float4* __restrict__ Q,  const float4* __restrict__ Kk,
                      uint2* __restrict__ WvH, uint2* __restrict__ WvL,
                      uint2* __restrict__ WoH, uint2* __restrict__ WoL,
                      uint2* __restrict__ WlH, uint2* __restrict__ WlL,
                      uint2* __restrict__ VaH, uint2* __restrict__ VaL,
                      uint2* __restrict__ QH,  uint2* __restrict__ QL,
                      uint2* __restrict__ KH,  uint2* __restrict__ KL)
{
    int b = blockIdx.x;
    const float4* src; uint2 *hi, *lo; int loc;
    if      (b < BL_WV)                        { src = Wv;  hi = WvH; lo = WvL; loc = b; }
    else if (b < 2 * BL_WV)                    { src = Wo;  hi = WoH; lo = WoL; loc = b - BL_WV; }
    else if (b < 2 * BL_WV + BL_WL)            { src = Wl;  hi = WlH; lo = WlL; loc = b - 2 * BL_WV; }
    else if (b < 2 * BL_WV + BL_WL + BL_X)     { src = Val; hi = VaH; lo = VaL; loc = b - 2 * BL_WV - BL_WL; }
    else if (b < 2 * BL_WV + BL_WL + 2 * BL_X) { src = Q;   hi = QH;  lo = QL;  loc = b - 2 * BL_WV - BL_WL - BL_X; }
    else                                       { src = Kk;  hi = KH;  lo = KL;  loc = b - 2 * BL_WV - BL_WL - 2 * BL_X; }
    int i = loc * 256 + threadIdx.x;
    float4 v = src[i];
    __nv_bfloat16 h0 = __float2bfloat16(v.x), h1 = __float2bfloat16(v.y);
    __nv_bfloat16 h2 = __float2bfloat16(v.z), h3 = __float2bfloat16(v.w);
    uint2 hv, lv;
    hv.x = (uint32_t)__bfloat16_as_ushort(h0) | ((uint32_t)__bfloat16_as_ushort(h1) << 16);
    hv.y = (uint32_t)__bfloat16_as_ushort(h2) | ((uint32_t)__bfloat16_as_ushort(h3) << 16);
    lv.x = pack_bf(v.x - __bfloat162float(h0), v.y - __bfloat162float(h1));
    lv.y = pack_bf(v.z - __bfloat162float(h2), v.w - __bfloat162float(h3));
    hi[i] = hv;
    lo[i] = lv;
}

// ---------------------------------------------------------------------------
// softmax over 2048 (key dim), scale 1/8; fp32 in, bf16 hi/lo out.
// ---------------------------------------------------------------------------
__global__ __launch_bounds__(256)
void softmax2048_kernel(const float* __restrict__ X, __nv_bfloat16* __restrict__ Hi,
                        __nv_bfloat16* __restrict__ Lo)
{
    const float* p = X + (long)blockIdx.x * 2048;
    int tid = threadIdx.x, lane = tid & 31, wid = tid >> 5;
    __shared__ float red[8];

    float v[8];
    float m = -3.4e38f;
#pragma unroll
    for (int i = 0; i < 8; i++) { v[i] = p[tid + 256 * i] * 0.125f; m = fmaxf(m, v[i]); }
#pragma unroll
    for (int o = 16; o; o >>= 1) m = fmaxf(m, __shfl_xor_sync(0xffffffffu, m, o));
    if (lane == 0) red[wid] = m;
    __syncthreads();
    float mm = red[0];
#pragma unroll
    for (int w = 1; w < 8; w++) mm = fmaxf(mm, red[w]);

    float s = 0.f;
#pragma unroll
    for (int i = 0; i < 8; i++) { v[i] = __expf(v[i] - mm); s += v[i]; }
#pragma unroll
    for (int o = 16; o; o >>= 1) s += __shfl_xor_sync(0xffffffffu, s, o);
    __syncthreads();
    if (lane == 0) red[wid] = s;
    __syncthreads();
    float ss = 0.f;
#pragma unroll
    for (int w = 0; w < 8; w++) ss += red[w];
    float inv = 1.0f / ss;

    long base = (long)blockIdx.x * 2048;
#pragma unroll
    for (int i = 0; i < 8; i++) {
        float f = v[i] * inv;
        __nv_bfloat16 h = __float2bfloat16(f);
        Hi[base + tid + 256 * i] = h;
        Lo[base + tid + 256 * i] = __float2bfloat16(f - __bfloat162float(h));
    }
}

// ---------------------------------------------------------------------------
// Host side
// ---------------------------------------------------------------------------
typedef CUresult (*TmaEncodeFn)(CUtensorMap*, CUtensorMapDataType, cuuint32_t, void*,
                                const cuuint64_t*, const cuuint64_t*,
                                const cuuint32_t*, const cuuint32_t*,
                                CUtensorMapInterleave, CUtensorMapSwizzle,
                                CUtensorMapL2promotion, CUtensorMapFloatOOBfill);

static void enc_tma(TmaEncodeFn fn, CUtensorMap* t, void* base,
                    long K, long rows, long Z, long zStrideElems)
{
    cuuint64_t dims[3] = {(cuuint64_t)K, (cuuint64_t)rows, (cuuint64_t)Z};
    cuuint64_t str[2]  = {(cuuint64_t)(K * 2), (cuuint64_t)(zStrideElems * 2)};
    cuuint32_t box[3]  = {KC, 128, 1};
    cuuint32_t es[3]   = {1, 1, 1};
    fn(t, CU_TENSOR_MAP_DATA_TYPE_UINT16, 3, base, dims, str, box, es,
       CU_TENSOR_MAP_INTERLEAVE_NONE, CU_TENSOR_MAP_SWIZZLE_64B,
       CU_TENSOR_MAP_L2_PROMOTION_L2_128B, CU_TENSOR_MAP_FLOAT_OOB_FILL_NONE);
}

extern "C" void kernel_launch(void* const* d_in, const int* in_sizes, int n_in,
                              void* d_out, int out_size)
{
    const float* query = (const float*)d_in[0];
    const float* key   = (const float*)d_in[1];
    const float* value = (const float*)d_in[2];
    const float* Wv    = (const float*)d_in[3];
    const float* bv    = (const float*)d_in[4];
    const float* Wl    = (const float*)d_in[5];
    const float* bl    = (const float*)d_in[6];
    const float* Wo    = (const float*)d_in[7];
    const float* bo    = (const float*)d_in[8];
    float* out = (float*)d_out;
    (void)in_sizes; (void)n_in; (void)out_size;

    cudaFuncSetAttribute(gemm_tma_kernel,
                         cudaFuncAttributeMaxDynamicSharedMemorySize, SMEM_TOTAL);

    TmaEncodeFn encode = nullptr;
    cudaDriverEntryPointQueryResult qr;
    cudaGetDriverEntryPointByVersion("cuTensorMapEncodeTiled", (void**)&encode,
                                     12000, cudaEnableDefault, &qr);

    __nv_bfloat16 *Wv_hi, *Wv_lo, *Wo_hi, *Wo_lo, *Wl_hi, *Wl_lo;
    __nv_bfloat16 *val_hi, *val_lo, *qk_hi, *qk_lo;
    __nv_bfloat16 *vpT_hi, *vpT_lo, *qkl_hi, *qkl_lo;
    __nv_bfloat16 *attn_hi, *attn_lo, *out2_hi, *out2_lo;
    float *attnf;
    cudaGetSymbolAddress((void**)&Wv_hi,  g_Wv_hi);  cudaGetSymbolAddress((void**)&Wv_lo,  g_Wv_lo);
    cudaGetSymbolAddress((void**)&Wo_hi,  g_Wo_hi);  cudaGetSymbolAddress((void**)&Wo_lo,  g_Wo_lo);
    cudaGetSymbolAddress((void**)&Wl_hi,  g_Wl_hi);  cudaGetSymbolAddress((void**)&Wl_lo,  g_Wl_lo);
    cudaGetSymbolAddress((void**)&val_hi, g_val_hi); cudaGetSymbolAddress((void**)&val_lo, g_val_lo);
    cudaGetSymbolAddress((void**)&qk_hi,  g_qk_hi);  cudaGetSymbolAddress((void**)&qk_lo,  g_qk_lo);
    cudaGetSymbolAddress((void**)&vpT_hi, g_vpT_hi); cudaGetSymbolAddress((void**)&vpT_lo, g_vpT_lo);
    cudaGetSymbolAddress((void**)&qkl_hi, g_qkl_hi); cudaGetSymbolAddress((void**)&qkl_lo, g_qkl_lo);
    cudaGetSymbolAddress((void**)&attn_hi, g_attn_hi); cudaGetSymbolAddress((void**)&attn_lo, g_attn_lo);
    cudaGetSymbolAddress((void**)&out2_hi, g_out2_hi); cudaGetSymbolAddress((void**)&out2_lo, g_out2_lo);
    cudaGetSymbolAddress((void**)&attnf, g_attn);

    dim3 blk(256);

    // 1) fused split of all six fp32 operands -> bf16 hi/lo
    split_all_kernel<<<SPLIT_BLOCKS, blk>>>(
        (const float4*)Wv, (const float4*)Wo, (const float4*)Wl,
        (const float4*)value, (const float4*)query, (const float4*)key,
        (uint2*)Wv_hi, (uint2*)Wv_lo, (uint2*)Wo_hi, (uint2*)Wo_lo,
        (uint2*)Wl_hi, (uint2*)Wl_lo, (uint2*)val_hi, (uint2*)val_lo,
        (uint2*)qk_hi, (uint2*)qk_lo,
        (uint2*)(qk_hi + (long)NTOK * EMB), (uint2*)(qk_lo + (long)NTOK * EMB));

    // --- tensormaps (host-side, capture-time only) ---
    CUtensorMap tWvH, tWvL, tValH, tValL, tQkH, tQkL, tWlH, tWlL;
    CUtensorMap tQlH, tQlL, tKlH, tKlL, tAtH, tAtL, tVpH, tVpL;
    CUtensorMap tO2H, tO2L, tWoH, tWoL;
    enc_tma(encode, &tWvH, Wv_hi, EMB, EMB, 1, (long)EMB * EMB);
    enc_tma(encode, &tWvL, Wv_lo, EMB, EMB, 1, (long)EMB * EMB);
    enc_tma(encode, &tValH, val_hi, EMB, LSEQ, BATCH, (long)LSEQ * EMB);
    enc_tma(encode, &tValL, val_lo, EMB, LSEQ, BATCH, (long)LSEQ * EMB);
    enc_tma(encode, &tQkH, qk_hi, EMB, 2 * NTOK, 1, (long)2 * NTOK * EMB);
    enc_tma(encode, &tQkL, qk_lo, EMB, 2 * NTOK, 1, (long)2 * NTOK * EMB);
    enc_tma(encode, &tWlH, Wl_hi, EMB, MLM, 1, (long)MLM * EMB);
    enc_tma(encode, &tWlL, Wl_lo, EMB, MLM, 1, (long)MLM * EMB);
    enc_tma(encode, &tQlH, qkl_hi, MLM, LSEQ, BATCH, (long)LSEQ * MLM);
    enc_tma(encode, &tQlL, qkl_lo, MLM, LSEQ, BATCH, (long)LSEQ * MLM);
    enc_tma(encode, &tKlH, qkl_hi + (long)NTOK * MLM, MLM, LSEQ, BATCH, (long)LSEQ * MLM);
    enc_tma(encode, &tKlL, qkl_lo + (long)NTOK * MLM, MLM, LSEQ, BATCH, (long)LSEQ * MLM);
    enc_tma(encode, &tAtH, attn_hi, LSEQ, LSEQ, BATCH, (long)LSEQ * LSEQ);
    enc_tma(encode, &tAtL, attn_lo, LSEQ, LSEQ, BATCH, (long)LSEQ * LSEQ);
    enc_tma(encode, &tVpH, vpT_hi, LSEQ, EMB, BATCH, (long)EMB * LSEQ);
    enc_tma(encode, &tVpL, vpT_lo, LSEQ, EMB, BATCH, (long)EMB * LSEQ);
    enc_tma(encode, &tO2H, out2_hi, EMB, NTOK, 1, (long)NTOK * EMB);
    enc_tma(encode, &tO2L, out2_lo, EMB, NTOK, 1, (long)NTOK * EMB);
    enc_tma(encode, &tWoH, Wo_hi, EMB, EMB, 1, (long)EMB * EMB);
    enc_tma(encode, &tWoL, Wo_lo, EMB, EMB, 1, (long)EMB * EMB);

    // 2) VprojT[b,e,k] = Wv x value^T + bv  -> bf16 hi/lo   (A=Wv, B=value[b])
    gemm_tma_kernel<<<dim3(LSEQ / TN, EMB / TM, BATCH), blk, SMEM_TOTAL>>>(
        tWvH, tWvL, tValH, tValL, nullptr, vpT_hi, vpT_lo,
        EMB, LSEQ, EMB, 0, 1, (long)EMB * LSEQ, bv, nullptr, 1);

    // 3) landmark logits (q|k, M=8192, N=64) + fused softmax64 -> qkl hi/lo
    gemm_tma_kernel<<<dim3(1, 2 * NTOK / TM, 1), blk, SMEM_TOTAL>>>(
        tQkH, tQkL, tWlH, tWlL, nullptr, qkl_hi, qkl_lo,
        2 * NTOK, MLM, EMB, 0, 0, 0L, nullptr, bl, 2);

    // 4) scores S[b,q,k] = ql . kl (K=64) -> fp32
    gemm_tma_kernel<<<dim3(LSEQ / TN, LSEQ / TM, BATCH), blk, SMEM_TOTAL>>>(
        tQlH, tQlL, tKlH, tKlL, attnf, nullptr, nullptr,
        LSEQ, LSEQ, MLM, 1, 1, (long)LSEQ * LSEQ, nullptr, nullptr, 0);

    // 5) softmax over keys -> bf16 hi/lo
    softmax2048_kernel<<<NTOK, blk>>>(attnf, attn_hi, attn_lo);

    // 6) out2[b,q,e] = attn x vpT (K=2048) -> bf16 hi/lo    [ncu -s5 lands here]
    gemm_tma_kernel<<<dim3(EMB / TN, LSEQ / TM, BATCH), blk, SMEM_TOTAL>>>(
        tAtH, tAtL, tVpH, tVpL, nullptr, out2_hi, out2_lo,
        LSEQ, EMB, LSEQ, 1, 1, (long)LSEQ * EMB, nullptr, nullptr, 1);

    // 7) out = out2 x Wo^T + bo -> fp32 d_out
    gemm_tma_kernel<<<dim3(EMB / TN, NTOK / TM, 1), blk, SMEM_TOTAL>>>(
        tO2H, tO2L, tWoH, tWoL, out, nullptr, nullptr,
        NTOK, EMB, EMB, 0, 0, 0L, nullptr, bo, 0);
}